// round 15
// baseline (speedup 1.0000x reference)
#include <cuda_runtime.h>
#include <cuda_fp16.h>
#include <cstdint>

#define B_   4096
#define G_   8
#define IN_  512
#define H_   1024
#define OUT_ 64

#define TM1    64
#define MAXT1  (B_ / TM1 + G_)   // 72
#define NCHUNK (H_ / 128)        // 8

// ---------------- gemm smem layout (per stage, bytes) ----------------
// A: 64 rows x 32k fp16 (hi+lo), stride 80B.  B: 32 k-rows x 128n fp16 hi, stride 272B
#define S1_A_HI 0
#define S1_A_LO 5120
#define S1_B_HI 10240
#define STAGE1  18944

// epilogue overlay (after mainloop)
#define EP_H_HI  0               // 64 rows x 272B = 17408
#define EP_H_LO  17408
#define EP_W2    34816           // 2 bufs x 4608 (hi only) -> end 44032
#define SMEM1    44032           // max(2*STAGE1=37888, 44032); x4 CTAs = 176128

// ---------------- device scratch ----------------
__device__ int d_perm[B_];
__device__ int t1_group[MAXT1], t1_start[MAXT1], t1_end[MAXT1];
__device__ int d_cnt[MAXT1];

__device__ __half d_xhi[(size_t)B_ * IN_];   // ORIGINAL row order (no gather)
__device__ __half d_xlo[(size_t)B_ * IN_];
__device__ __half d_w1h[(size_t)G_ * IN_ * H_];
__device__ __half d_w2h[(size_t)G_ * H_ * OUT_];
__device__ float d_ypart[(size_t)NCHUNK * B_ * OUT_];   // 8 MB

// ---------------- asm helpers ----------------
__device__ __forceinline__ uint32_t smem_u32(const void* p) {
    uint32_t a;
    asm("{ .reg .u64 t; cvta.to.shared.u64 t, %1; cvt.u32.u64 %0, t; }" : "=r"(a) : "l"(p));
    return a;
}
__device__ __forceinline__ void cp16(uint32_t s, const void* g, int srcsz) {
    asm volatile("cp.async.cg.shared.global [%0], [%1], 16, %2;"
                 :: "r"(s), "l"(g), "r"(srcsz) : "memory");
}
#define CP_COMMIT() asm volatile("cp.async.commit_group;" ::: "memory")
#define CP_WAIT1()  asm volatile("cp.async.wait_group 1;" ::: "memory")
#define CP_WAIT0()  asm volatile("cp.async.wait_group 0;" ::: "memory")

#define LDSM_X4(r, a)                                                            \
    asm volatile("ldmatrix.sync.aligned.m8n8.x4.shared.b16 {%0,%1,%2,%3}, [%4];" \
                 : "=r"((r)[0]), "=r"((r)[1]), "=r"((r)[2]), "=r"((r)[3]) : "r"(a))
#define LDSM_X4T(r, a)                                                                 \
    asm volatile("ldmatrix.sync.aligned.m8n8.x4.trans.shared.b16 {%0,%1,%2,%3}, [%4];" \
                 : "=r"((r)[0]), "=r"((r)[1]), "=r"((r)[2]), "=r"((r)[3]) : "r"(a))

#define MMA16816(c, a, b0, b1)                                                    \
    asm volatile("mma.sync.aligned.m16n8k16.row.col.f32.f16.f16.f32 "             \
                 "{%0,%1,%2,%3}, {%4,%5,%6,%7}, {%8,%9}, {%0,%1,%2,%3};"          \
                 : "+f"((c)[0]), "+f"((c)[1]), "+f"((c)[2]), "+f"((c)[3])         \
                 : "r"((a)[0]), "r"((a)[1]), "r"((a)[2]), "r"((a)[3]),            \
                   "r"(b0), "r"(b1))

__device__ __forceinline__ uint32_t pack_h2(float a, float b) {
    __half2 t = __floats2half2_rn(a, b);
    return *reinterpret_cast<uint32_t*>(&t);
}
__device__ __forceinline__ void split8h(const float* v, uint4& hi, uint4& lo) {
    float h[8], l[8];
#pragma unroll
    for (int i = 0; i < 8; i++) {
        __half hh = __float2half_rn(v[i]);
        h[i] = __half2float(hh);
        l[i] = v[i] - h[i];
    }
    hi = make_uint4(pack_h2(h[0], h[1]), pack_h2(h[2], h[3]),
                    pack_h2(h[4], h[5]), pack_h2(h[6], h[7]));
    lo = make_uint4(pack_h2(l[0], l[1]), pack_h2(l[2], l[3]),
                    pack_h2(l[4], l[5]), pack_h2(l[6], l[7]));
}
__device__ __forceinline__ uint4 pack8h(const float* v) {
    return make_uint4(pack_h2(v[0], v[1]), pack_h2(v[2], v[3]),
                      pack_h2(v[4], v[5]), pack_h2(v[6], v[7]));
}

__device__ __forceinline__ void cvt32_pair(const float* __restrict__ src, size_t soff,
                                           __half* dhi, __half* dlo, size_t doff) {
    float4 q[8];
    const float4* p = reinterpret_cast<const float4*>(src + soff);
#pragma unroll
    for (int i = 0; i < 8; i++) q[i] = p[i];
    uint4* ph = reinterpret_cast<uint4*>(dhi + doff);
    uint4* pl = reinterpret_cast<uint4*>(dlo + doff);
#pragma unroll
    for (int i = 0; i < 4; i++) {
        float v[8] = {q[2*i].x, q[2*i].y, q[2*i].z, q[2*i].w,
                      q[2*i+1].x, q[2*i+1].y, q[2*i+1].z, q[2*i+1].w};
        uint4 hi, lo;
        split8h(v, hi, lo);
        ph[i] = hi;
        pl[i] = lo;
    }
}

__device__ __forceinline__ void cvt32_hi(const float* __restrict__ src, size_t soff,
                                         __half* dhi, size_t doff) {
    float4 q[8];
    const float4* p = reinterpret_cast<const float4*>(src + soff);
#pragma unroll
    for (int i = 0; i < 8; i++) q[i] = p[i];
    uint4* ph = reinterpret_cast<uint4*>(dhi + doff);
#pragma unroll
    for (int i = 0; i < 4; i++) {
        float v[8] = {q[2*i].x, q[2*i].y, q[2*i].z, q[2*i].w,
                      q[2*i+1].x, q[2*i+1].y, q[2*i+1].z, q[2*i+1].w};
        ph[i] = pack8h(v);
    }
}

// ---------------- front kernel: block 0 = atomic-free route, blocks 1.. = convert
#define FR_XB  64
#define FR_W1B 128
#define FR_W2B 16
#define FR_NB  (1 + FR_XB + FR_W1B + FR_W2B)
#define NW     32                 // warps in route block

__global__ __launch_bounds__(1024) void k_front(const int* __restrict__ gid,
                                                const float* __restrict__ x,
                                                const float* __restrict__ W1,
                                                const float* __restrict__ W2) {
    __shared__ int s_gid[B_];
    __shared__ int s_wexcl[NW * G_];
    __shared__ int s_total[G_];
    __shared__ int s_base[G_];
    int b = blockIdx.x;
    int tid = threadIdx.x;

    if (b == 0) {
        // ---- atomic-free stable counting sort by gid ----
        int lane = tid & 31;
        int w = tid >> 5;             // 0..31
        if (tid < MAXT1) d_cnt[tid] = 0;

        // phase A: load gid, cache, per-warp histogram in registers (lane g counts group g)
        int cnt = 0;
#pragma unroll
        for (int j = 0; j < B_ / 1024; j++) {
            int i = tid + 1024 * j;
            int g = __ldg(gid + i);
            s_gid[i] = g;
#pragma unroll
            for (int t = 0; t < G_; t++) {
                unsigned bal = __ballot_sync(0xffffffffu, g == t);
                if (lane == t) cnt += __popc(bal);
            }
        }
        if (lane < G_) s_wexcl[w * G_ + lane] = cnt;   // temporarily store counts
        __syncthreads();

        // phase B: per-group exclusive scan over the 32 warp-counts (warp g scans group g)
        if (w < G_) {
            int v = s_wexcl[lane * G_ + w];
            int s = v;
#pragma unroll
            for (int d = 1; d < 32; d <<= 1) {
                int t = __shfl_up_sync(0xffffffffu, s, d);
                if (lane >= d) s += t;
            }
            s_wexcl[lane * G_ + w] = s - v;            // exclusive
            if (lane == 31) s_total[w] = s;
        }
        __syncthreads();
        if (tid == 0) {
            int offs[G_ + 1];
            offs[0] = 0;
            for (int g = 0; g < G_; g++) { offs[g + 1] = offs[g] + s_total[g]; s_base[g] = offs[g]; }
            int t = 0;
            for (int g = 0; g < G_; g++)
                for (int r = offs[g]; r < offs[g + 1]; r += TM1) {
                    t1_group[t] = g; t1_start[t] = r;
                    t1_end[t] = min(r + TM1, offs[g + 1]);
                    t++;
                }
            for (; t < MAXT1; t++) t1_group[t] = -1;
        }
        __syncthreads();

        // phase C: rank + scatter (lane g holds running offset for group g)
        int run = 0;
        if (lane < G_) run = s_base[lane] + s_wexcl[w * G_ + lane];
#pragma unroll
        for (int j = 0; j < B_ / 1024; j++) {
            int i = tid + 1024 * j;
            int g = s_gid[i];
            unsigned m = __match_any_sync(0xffffffffu, g);
            int rank = __popc(m & ((1u << lane) - 1));
            int base = __shfl_sync(0xffffffffu, run, g);
            d_perm[base + rank] = i;
#pragma unroll
            for (int t = 0; t < G_; t++) {
                unsigned bal = __ballot_sync(0xffffffffu, g == t);
                if (lane == t) run += __popc(bal);
            }
        }
    } else if (b <= FR_XB) {
        size_t u = (size_t)(b - 1) * 1024 + tid;
        cvt32_pair(x, u * 32, d_xhi, d_xlo, u * 32);
    } else if (b <= FR_XB + FR_W1B) {
        size_t u = (size_t)(b - 1 - FR_XB) * 1024 + tid;
        cvt32_hi(W1, u * 32, d_w1h, u * 32);
    } else {
        size_t u = (size_t)(b - 1 - FR_XB - FR_W1B) * 1024 + tid;
        cvt32_hi(W2, u * 32, d_w2h, u * 32);
    }
}

// ---------------- fused gemm + layer2 + deterministic fix-up reduction ----
// 64x128 tile, 128 threads, 4 CTAs/SM; single-sync mainloop
__global__ __launch_bounds__(128, 4) void k_gemm(const float* __restrict__ b1,
                                                 const float* __restrict__ b2,
                                                 float* __restrict__ y) {
    int tile = blockIdx.x;
    int g = t1_group[tile];
    if (g < 0) return;
    int rs = t1_start[tile], re = t1_end[tile];
    int cc = blockIdx.y;
    int n0 = cc * 128;

    extern __shared__ char sm[];
    __shared__ int s_perm[TM1];
    __shared__ int s_done;
    uint32_t smb = smem_u32(sm);
    int tid = threadIdx.x;
    int lane = tid & 31;
    int wid = tid >> 5;
    int warp_m = wid >> 1, warp_n = wid & 1;

    if (tid < TM1) {
        int gr = rs + tid;
        s_perm[tid] = d_perm[(gr < re) ? gr : rs];
    }
    __syncthreads();

    const __half* w1h = d_w1h + (size_t)g * IN_ * H_;
    const __half* w2h = d_w2h + (size_t)g * H_ * OUT_;

#define STAGE_G1(bi, ch) do {                                                    \
    int k0 = (ch) * 32;                                                          \
    uint32_t sb = smb + (bi) * STAGE1;                                           \
    _Pragma("unroll")                                                            \
    for (int j = 0; j < 2; j++) {                                                \
        int c = tid + 128 * j;                                                   \
        int row = c >> 2, seg = c & 3;                                           \
        int ok = (rs + row < re) ? 16 : 0;                                       \
        size_t go = (size_t)s_perm[row] * IN_ + k0 + seg * 8;                    \
        uint32_t so = row * 80 + seg * 16;                                       \
        cp16(sb + S1_A_HI + so, d_xhi + go, ok);                                 \
        cp16(sb + S1_A_LO + so, d_xlo + go, ok);                                 \
    }                                                                            \
    _Pragma("unroll")                                                            \
    for (int j = 0; j < 4; j++) {                                                \
        int c = tid + 128 * j;                                                   \
        int row = c >> 4, seg = c & 15;                                          \
        size_t go = (size_t)(k0 + row) * H_ + n0 + seg * 8;                      \
        uint32_t so = row * 272 + seg * 16;                                      \
        cp16(sb + S1_B_HI + so, w1h + go, 16);                                   \
    }                                                                            \
} while (0)

    float acc[2][8][4];
#pragma unroll
    for (int t = 0; t < 2; t++)
#pragma unroll
        for (int n = 0; n < 8; n++)
#pragma unroll
            for (int r = 0; r < 4; r++) acc[t][n][r] = 0.f;

    STAGE_G1(0, 0);
    CP_COMMIT();

    const int NCH = IN_ / 32;   // 16
    for (int ch = 0; ch < NCH; ch++) {
        CP_WAIT0();              // only group ch is outstanding
        __syncthreads();         // data visible + all warps done with prev compute
        if (ch + 1 < NCH) { STAGE_G1((ch + 1) & 1, ch + 1); CP_COMMIT(); }

        uint32_t sb = smb + (ch & 1) * STAGE1;
#pragma unroll
        for (int kk = 0; kk < 2; kk++) {
            uint32_t ah[2][4], al[2][4];
#pragma unroll
            for (int t = 0; t < 2; t++) {
                uint32_t ao = (warp_m * 32 + t * 16 + (lane & 15)) * 80
                            + kk * 32 + (lane >> 4) * 16;
                LDSM_X4(ah[t], sb + S1_A_HI + ao);
                LDSM_X4(al[t], sb + S1_A_LO + ao);
            }
#pragma unroll
            for (int q = 0; q < 4; q++) {
                uint32_t bh[4];
                uint32_t bo = (kk * 16 + (lane & 15)) * 272
                            + (warp_n * 64 + q * 16) * 2 + (lane >> 4) * 16;
                LDSM_X4T(bh, sb + S1_B_HI + bo);
                int nq = q * 2;
#pragma unroll
                for (int t = 0; t < 2; t++) {
                    MMA16816(acc[t][nq],     ah[t], bh[0], bh[1]);
                    MMA16816(acc[t][nq + 1], ah[t], bh[2], bh[3]);
                }
#pragma unroll
                for (int t = 0; t < 2; t++) {
                    MMA16816(acc[t][nq],     al[t], bh[0], bh[1]);
                    MMA16816(acc[t][nq + 1], al[t], bh[2], bh[3]);
                }
            }
        }
    }
#undef STAGE_G1
    __syncthreads();    // all warps done with last chunk before epilogue overlays stage smem

    // ======== fused layer-2 epilogue (2-pass fp16: h hi+lo, W2 hi only) ========
#define STAGE_W2(bi, s) do {                                                     \
    int kk0 = n0 + (s) * 32;                                                     \
    uint32_t wb = smb + EP_W2 + (bi) * 4608;                                     \
    _Pragma("unroll")                                                            \
    for (int j = 0; j < 2; j++) {                                                \
        int c = tid + 128 * j;                                                   \
        int row = c >> 3, seg = c & 7;                                           \
        size_t go = (size_t)(kk0 + row) * OUT_ + seg * 8;                        \
        uint32_t so = row * 144 + seg * 16;                                      \
        cp16(wb + so, w2h + go, 16);                                             \
    }                                                                            \
} while (0)

    STAGE_W2(0, 0); CP_COMMIT();
    STAGE_W2(1, 1); CP_COMMIT();

    // write h = relu(acc + b1) into smem as fp16 hi/lo (zero for invalid rows)
    const float* b1g = b1 + g * H_;
#pragma unroll
    for (int n = 0; n < 8; n++) {
        int col = warp_n * 64 + n * 8 + (lane & 3) * 2;     // local 0..127
        float bb0 = __ldg(b1g + n0 + col), bb1 = __ldg(b1g + n0 + col + 1);
#pragma unroll
        for (int t = 0; t < 2; t++) {
            int row0 = warp_m * 32 + t * 16 + (lane >> 2);  // local 0..63
            {
                bool val = (rs + row0 < re);
                float v0 = val ? fmaxf(acc[t][n][0] + bb0, 0.f) : 0.f;
                float v1 = val ? fmaxf(acc[t][n][1] + bb1, 0.f) : 0.f;
                float h0 = __half2float(__float2half_rn(v0));
                float h1 = __half2float(__float2half_rn(v1));
                uint32_t off = row0 * 272 + col * 2;
                *reinterpret_cast<uint32_t*>(sm + EP_H_HI + off) = pack_h2(h0, h1);
                *reinterpret_cast<uint32_t*>(sm + EP_H_LO + off) = pack_h2(v0 - h0, v1 - h1);
            }
            {
                int row1 = row0 + 8;
                bool val = (rs + row1 < re);
                float v0 = val ? fmaxf(acc[t][n][2] + bb0, 0.f) : 0.f;
                float v1 = val ? fmaxf(acc[t][n][3] + bb1, 0.f) : 0.f;
                float h0 = __half2float(__float2half_rn(v0));
                float h1 = __half2float(__float2half_rn(v1));
                uint32_t off = row1 * 272 + col * 2;
                *reinterpret_cast<uint32_t*>(sm + EP_H_HI + off) = pack_h2(h0, h1);
                *reinterpret_cast<uint32_t*>(sm + EP_H_LO + off) = pack_h2(v0 - h0, v1 - h1);
            }
        }
    }

    // y partial: each warp computes rows [wid*16, wid*16+16) x 64 cols
    float ya[8][4];
#pragma unroll
    for (int n = 0; n < 8; n++)
#pragma unroll
        for (int r = 0; r < 4; r++) ya[n][r] = 0.f;

    CP_WAIT1();          // subchunk 0 resident
    __syncthreads();     // h + W2 buf0 visible to all

#pragma unroll
    for (int s = 0; s < 4; s++) {
        uint32_t wb = smb + EP_W2 + (s & 1) * 4608;
#pragma unroll
        for (int j = 0; j < 2; j++) {
            uint32_t ah[4], al[4];
            uint32_t ao = (wid * 16 + (lane & 15)) * 272
                        + s * 64 + j * 32 + (lane >> 4) * 16;
            LDSM_X4(ah, smb + EP_H_HI + ao);
            LDSM_X4(al, smb + EP_H_LO + ao);
#pragma unroll
            for (int q = 0; q < 4; q++) {
                uint32_t bh[4];
                uint32_t bo = (j * 16 + (lane & 15)) * 144 + q * 32 + (lane >> 4) * 16;
                LDSM_X4T(bh, wb + bo);
                int nq = q * 2;
                MMA16816(ya[nq],     ah, bh[0], bh[1]);
                MMA16816(ya[nq + 1], ah, bh[2], bh[3]);
                MMA16816(ya[nq],     al, bh[0], bh[1]);
                MMA16816(ya[nq + 1], al, bh[2], bh[3]);
            }
        }
        if (s < 2) {
            __syncthreads();                 // buf (s&1) fully consumed by all warps
            if (s + 2 < 4) { STAGE_W2(s & 1, s + 2); CP_COMMIT(); }
            if (s == 0) CP_WAIT1(); else CP_WAIT0();
            __syncthreads();
        } else if (s == 2) {
            CP_WAIT0();
            __syncthreads();
        }
    }
#undef STAGE_W2

    // write 64x64 fp32 partial
    float* yp = d_ypart + (size_t)cc * B_ * OUT_;
#pragma unroll
    for (int n = 0; n < 8; n++) {
        int col = n * 8 + (lane & 3) * 2;
        int r0 = rs + wid * 16 + (lane >> 2);
        if (r0 < re) {
            float2 v = make_float2(ya[n][0], ya[n][1]);
            *reinterpret_cast<float2*>(yp + (size_t)r0 * OUT_ + col) = v;
        }
        int r1 = r0 + 8;
        if (r1 < re) {
            float2 v = make_float2(ya[n][2], ya[n][3]);
            *reinterpret_cast<float2*>(yp + (size_t)r1 * OUT_ + col) = v;
        }
    }

    // ======== deterministic fix-up: last CTA of this tile reduces all chunks ====
    __threadfence();
    __syncthreads();
    if (tid == 0) s_done = atomicAdd(&d_cnt[tile], 1);
    __syncthreads();
    if (s_done == NCHUNK - 1) {
        __threadfence();
        int nrows = re - rs;
        const float* b2g = b2 + g * OUT_;
        for (int u = tid; u < nrows * 16; u += 128) {
            int r = u >> 4;
            int o = (u & 15) * 4;
            int gr = rs + r;
            float4 a = *reinterpret_cast<const float4*>(b2g + o);
#pragma unroll
            for (int c = 0; c < NCHUNK; c++) {
                float4 v = __ldcg(reinterpret_cast<const float4*>(
                    d_ypart + ((size_t)c * B_ + gr) * OUT_ + o));
                a.x += v.x; a.y += v.y; a.z += v.z; a.w += v.w;
            }
            *reinterpret_cast<float4*>(y + (size_t)s_perm[r] * OUT_ + o) = a;
        }
    }
}

// ---------------- launch ----------------
extern "C" void kernel_launch(void* const* d_in, const int* in_sizes, int n_in,
                              void* d_out, int out_size) {
    const float* x   = (const float*)d_in[0];
    const int*   gid = (const int*)  d_in[1];
    const float* W1  = (const float*)d_in[2];
    const float* b1  = (const float*)d_in[3];
    const float* W2  = (const float*)d_in[4];
    const float* b2  = (const float*)d_in[5];
    float* y = (float*)d_out;

    static bool attr_set = false;
    if (!attr_set) {
        cudaFuncSetAttribute(k_gemm, cudaFuncAttributeMaxDynamicSharedMemorySize, SMEM1);
        attr_set = true;
    }

    k_front<<<FR_NB, 1024>>>(gid, x, W1, W2);
    dim3 g1(MAXT1, NCHUNK);
    k_gemm<<<g1, 128, SMEM1>>>(b1, b2, y);
}

// round 16
// speedup vs baseline: 1.2553x; 1.2553x over previous
#include <cuda_runtime.h>
#include <cuda_fp16.h>
#include <cstdint>

#define B_   4096
#define G_   8
#define IN_  512
#define H_   1024
#define OUT_ 64

#define TM1    64
#define MAXT1  (B_ / TM1 + G_)   // 72
#define NCHUNK (H_ / 128)        // 8

// ---------------- gemm smem layout (per stage, bytes) ----------------
// A: 64 rows x 32k fp16 hi, stride 80B.  B: 32 k-rows x 128n fp16 hi, stride 272B
#define S1_A_HI 0
#define S1_B_HI 5120
#define STAGE1  13824

// epilogue overlay (after mainloop)
#define EP_H_HI  0               // 64 rows x 272B = 17408
#define EP_H_LO  17408
#define EP_W2    34816           // 2 bufs x 4608 (hi only) -> end 44032
#define SMEM1    44032           // max(2*STAGE1=27648, 44032); x4 CTAs = 176128

// ---------------- device scratch ----------------
__device__ int d_perm[B_];
__device__ int t1_group[MAXT1], t1_start[MAXT1], t1_end[MAXT1];
__device__ int d_cnt[MAXT1];

__device__ __half d_xhi[(size_t)B_ * IN_];   // ORIGINAL row order
__device__ __half d_w1h[(size_t)G_ * IN_ * H_];
__device__ __half d_w2h[(size_t)G_ * H_ * OUT_];
__device__ float d_ypart[(size_t)NCHUNK * B_ * OUT_];   // 8 MB

// ---------------- asm helpers ----------------
__device__ __forceinline__ uint32_t smem_u32(const void* p) {
    uint32_t a;
    asm("{ .reg .u64 t; cvta.to.shared.u64 t, %1; cvt.u32.u64 %0, t; }" : "=r"(a) : "l"(p));
    return a;
}
__device__ __forceinline__ void cp16(uint32_t s, const void* g, int srcsz) {
    asm volatile("cp.async.cg.shared.global [%0], [%1], 16, %2;"
                 :: "r"(s), "l"(g), "r"(srcsz) : "memory");
}
#define CP_COMMIT() asm volatile("cp.async.commit_group;" ::: "memory")
#define CP_WAIT1()  asm volatile("cp.async.wait_group 1;" ::: "memory")
#define CP_WAIT0()  asm volatile("cp.async.wait_group 0;" ::: "memory")

#define LDSM_X4(r, a)                                                            \
    asm volatile("ldmatrix.sync.aligned.m8n8.x4.shared.b16 {%0,%1,%2,%3}, [%4];" \
                 : "=r"((r)[0]), "=r"((r)[1]), "=r"((r)[2]), "=r"((r)[3]) : "r"(a))
#define LDSM_X4T(r, a)                                                                 \
    asm volatile("ldmatrix.sync.aligned.m8n8.x4.trans.shared.b16 {%0,%1,%2,%3}, [%4];" \
                 : "=r"((r)[0]), "=r"((r)[1]), "=r"((r)[2]), "=r"((r)[3]) : "r"(a))

#define MMA16816(c, a, b0, b1)                                                    \
    asm volatile("mma.sync.aligned.m16n8k16.row.col.f32.f16.f16.f32 "             \
                 "{%0,%1,%2,%3}, {%4,%5,%6,%7}, {%8,%9}, {%0,%1,%2,%3};"          \
                 : "+f"((c)[0]), "+f"((c)[1]), "+f"((c)[2]), "+f"((c)[3])         \
                 : "r"((a)[0]), "r"((a)[1]), "r"((a)[2]), "r"((a)[3]),            \
                   "r"(b0), "r"(b1))

__device__ __forceinline__ uint32_t pack_h2(float a, float b) {
    __half2 t = __floats2half2_rn(a, b);
    return *reinterpret_cast<uint32_t*>(&t);
}
__device__ __forceinline__ uint4 pack8h(const float* v) {
    return make_uint4(pack_h2(v[0], v[1]), pack_h2(v[2], v[3]),
                      pack_h2(v[4], v[5]), pack_h2(v[6], v[7]));
}
__device__ __forceinline__ void cvt32_hi(const float* __restrict__ src, size_t soff,
                                         __half* dhi, size_t doff) {
    float4 q[8];
    const float4* p = reinterpret_cast<const float4*>(src + soff);
#pragma unroll
    for (int i = 0; i < 8; i++) q[i] = p[i];
    uint4* ph = reinterpret_cast<uint4*>(dhi + doff);
#pragma unroll
    for (int i = 0; i < 4; i++) {
        float v[8] = {q[2*i].x, q[2*i].y, q[2*i].z, q[2*i].w,
                      q[2*i+1].x, q[2*i+1].y, q[2*i+1].z, q[2*i+1].w};
        ph[i] = pack8h(v);
    }
}

// ---------------- front kernel: block 0 = route, blocks 1.. = convert ----
// x: 64 blocks, W1: 128 blocks, W2: 16 blocks  -> grid = 209, 1024 threads
#define FR_XB  64
#define FR_W1B 128
#define FR_W2B 16
#define FR_NB  (1 + FR_XB + FR_W1B + FR_W2B)

__global__ __launch_bounds__(1024) void k_front(const int* __restrict__ gid,
                                                const float* __restrict__ x,
                                                const float* __restrict__ W1,
                                                const float* __restrict__ W2) {
    __shared__ int s_gid[B_];
    __shared__ int hist[G_];
    __shared__ int cur[G_];
    int b = blockIdx.x;
    int tid = threadIdx.x;

    if (b == 0) {
        // ---- routing: histogram + plan + scatter ----
        int lane = tid & 31;
        if (tid < G_) hist[tid] = 0;
        if (tid < MAXT1) d_cnt[tid] = 0;
        __syncthreads();
#pragma unroll
        for (int j = 0; j < B_ / 1024; j++) {
            int i = tid + 1024 * j;
            int g = __ldg(gid + i);
            s_gid[i] = g;
            unsigned mask = __match_any_sync(0xffffffffu, g);
            int leader = __ffs(mask) - 1;
            if (lane == leader) atomicAdd(&hist[g], __popc(mask));
        }
        __syncthreads();
        if (tid == 0) {
            int offs[G_ + 1];
            offs[0] = 0;
            for (int g = 0; g < G_; g++) offs[g + 1] = offs[g] + hist[g];
            for (int g = 0; g < G_; g++) cur[g] = offs[g];
            int t = 0;
            for (int g = 0; g < G_; g++)
                for (int r = offs[g]; r < offs[g + 1]; r += TM1) {
                    t1_group[t] = g; t1_start[t] = r;
                    t1_end[t] = min(r + TM1, offs[g + 1]);
                    t++;
                }
            for (; t < MAXT1; t++) t1_group[t] = -1;
        }
        __syncthreads();
#pragma unroll
        for (int j = 0; j < B_ / 1024; j++) {
            int i = tid + 1024 * j;
            int g = s_gid[i];
            unsigned mask = __match_any_sync(0xffffffffu, g);
            int leader = __ffs(mask) - 1;
            int rank = __popc(mask & ((1u << lane) - 1));
            int base = 0;
            if (lane == leader) base = atomicAdd(&cur[g], __popc(mask));
            base = __shfl_sync(0xffffffffu, base, leader);
            d_perm[base + rank] = i;
        }
    } else if (b <= FR_XB) {
        size_t u = (size_t)(b - 1) * 1024 + tid;
        cvt32_hi(x, u * 32, d_xhi, u * 32);
    } else if (b <= FR_XB + FR_W1B) {
        size_t u = (size_t)(b - 1 - FR_XB) * 1024 + tid;
        cvt32_hi(W1, u * 32, d_w1h, u * 32);
    } else {
        size_t u = (size_t)(b - 1 - FR_XB - FR_W1B) * 1024 + tid;
        cvt32_hi(W2, u * 32, d_w2h, u * 32);
    }
}

// ---------------- fused gemm + layer2 + deterministic fix-up reduction ----
// 64x128 tile, 128 threads, 4 CTAs/SM; PURE-fp16 single-pass mainloop
__global__ __launch_bounds__(128, 4) void k_gemm(const float* __restrict__ b1,
                                                 const float* __restrict__ b2,
                                                 float* __restrict__ y) {
    int tile = blockIdx.x;
    int g = t1_group[tile];
    if (g < 0) return;
    int rs = t1_start[tile], re = t1_end[tile];
    int cc = blockIdx.y;
    int n0 = cc * 128;

    extern __shared__ char sm[];
    __shared__ int s_perm[TM1];
    __shared__ int s_done;
    uint32_t smb = smem_u32(sm);
    int tid = threadIdx.x;
    int lane = tid & 31;
    int wid = tid >> 5;
    int warp_m = wid >> 1, warp_n = wid & 1;

    if (tid < TM1) {
        int gr = rs + tid;
        s_perm[tid] = d_perm[(gr < re) ? gr : rs];
    }
    __syncthreads();

    const __half* w1h = d_w1h + (size_t)g * IN_ * H_;
    const __half* w2h = d_w2h + (size_t)g * H_ * OUT_;

#define STAGE_G1(bi, ch) do {                                                    \
    int k0 = (ch) * 32;                                                          \
    uint32_t sb = smb + (bi) * STAGE1;                                           \
    _Pragma("unroll")                                                            \
    for (int j = 0; j < 2; j++) {                                                \
        int c = tid + 128 * j;                                                   \
        int row = c >> 2, seg = c & 3;                                           \
        int ok = (rs + row < re) ? 16 : 0;                                       \
        size_t go = (size_t)s_perm[row] * IN_ + k0 + seg * 8;                    \
        uint32_t so = row * 80 + seg * 16;                                       \
        cp16(sb + S1_A_HI + so, d_xhi + go, ok);                                 \
    }                                                                            \
    _Pragma("unroll")                                                            \
    for (int j = 0; j < 4; j++) {                                                \
        int c = tid + 128 * j;                                                   \
        int row = c >> 4, seg = c & 15;                                          \
        size_t go = (size_t)(k0 + row) * H_ + n0 + seg * 8;                      \
        uint32_t so = row * 272 + seg * 16;                                      \
        cp16(sb + S1_B_HI + so, w1h + go, 16);                                   \
    }                                                                            \
} while (0)

    float acc[2][8][4];
#pragma unroll
    for (int t = 0; t < 2; t++)
#pragma unroll
        for (int n = 0; n < 8; n++)
#pragma unroll
            for (int r = 0; r < 4; r++) acc[t][n][r] = 0.f;

    STAGE_G1(0, 0);
    CP_COMMIT();

    const int NCH = IN_ / 32;   // 16
    for (int ch = 0; ch < NCH; ch++) {
        if (ch + 1 < NCH) { STAGE_G1((ch + 1) & 1, ch + 1); CP_COMMIT(); CP_WAIT1(); }
        else CP_WAIT0();
        __syncthreads();

        uint32_t sb = smb + (ch & 1) * STAGE1;
#pragma unroll
        for (int kk = 0; kk < 2; kk++) {
            uint32_t ah[2][4];
#pragma unroll
            for (int t = 0; t < 2; t++) {
                uint32_t ao = (warp_m * 32 + t * 16 + (lane & 15)) * 80
                            + kk * 32 + (lane >> 4) * 16;
                LDSM_X4(ah[t], sb + S1_A_HI + ao);
            }
#pragma unroll
            for (int q = 0; q < 4; q++) {
                uint32_t bh[4];
                uint32_t bo = (kk * 16 + (lane & 15)) * 272
                            + (warp_n * 64 + q * 16) * 2 + (lane >> 4) * 16;
                LDSM_X4T(bh, sb + S1_B_HI + bo);
                int nq = q * 2;
#pragma unroll
                for (int t = 0; t < 2; t++) {
                    MMA16816(acc[t][nq],     ah[t], bh[0], bh[1]);
                    MMA16816(acc[t][nq + 1], ah[t], bh[2], bh[3]);
                }
            }
        }
        __syncthreads();
    }
#undef STAGE_G1

    // ======== fused layer-2 epilogue (2-pass fp16: h hi+lo, W2 hi only) ========
#define STAGE_W2(bi, s) do {                                                     \
    int kk0 = n0 + (s) * 32;                                                     \
    uint32_t wb = smb + EP_W2 + (bi) * 4608;                                     \
    _Pragma("unroll")                                                            \
    for (int j = 0; j < 2; j++) {                                                \
        int c = tid + 128 * j;                                                   \
        int row = c >> 3, seg = c & 7;                                           \
        size_t go = (size_t)(kk0 + row) * OUT_ + seg * 8;                        \
        uint32_t so = row * 144 + seg * 16;                                      \
        cp16(wb + so, w2h + go, 16);                                             \
    }                                                                            \
} while (0)

    STAGE_W2(0, 0); CP_COMMIT();
    STAGE_W2(1, 1); CP_COMMIT();

    // write h = relu(acc + b1) into smem as fp16 hi/lo (zero for invalid rows)
    const float* b1g = b1 + g * H_;
#pragma unroll
    for (int n = 0; n < 8; n++) {
        int col = warp_n * 64 + n * 8 + (lane & 3) * 2;     // local 0..127
        float bb0 = __ldg(b1g + n0 + col), bb1 = __ldg(b1g + n0 + col + 1);
#pragma unroll
        for (int t = 0; t < 2; t++) {
            int row0 = warp_m * 32 + t * 16 + (lane >> 2);  // local 0..63
            {
                bool val = (rs + row0 < re);
                float v0 = val ? fmaxf(acc[t][n][0] + bb0, 0.f) : 0.f;
                float v1 = val ? fmaxf(acc[t][n][1] + bb1, 0.f) : 0.f;
                float h0 = __half2float(__float2half_rn(v0));
                float h1 = __half2float(__float2half_rn(v1));
                uint32_t off = row0 * 272 + col * 2;
                *reinterpret_cast<uint32_t*>(sm + EP_H_HI + off) = pack_h2(h0, h1);
                *reinterpret_cast<uint32_t*>(sm + EP_H_LO + off) = pack_h2(v0 - h0, v1 - h1);
            }
            {
                int row1 = row0 + 8;
                bool val = (rs + row1 < re);
                float v0 = val ? fmaxf(acc[t][n][2] + bb0, 0.f) : 0.f;
                float v1 = val ? fmaxf(acc[t][n][3] + bb1, 0.f) : 0.f;
                float h0 = __half2float(__float2half_rn(v0));
                float h1 = __half2float(__float2half_rn(v1));
                uint32_t off = row1 * 272 + col * 2;
                *reinterpret_cast<uint32_t*>(sm + EP_H_HI + off) = pack_h2(h0, h1);
                *reinterpret_cast<uint32_t*>(sm + EP_H_LO + off) = pack_h2(v0 - h0, v1 - h1);
            }
        }
    }

    // y partial: each warp computes rows [wid*16, wid*16+16) x 64 cols
    float ya[8][4];
#pragma unroll
    for (int n = 0; n < 8; n++)
#pragma unroll
        for (int r = 0; r < 4; r++) ya[n][r] = 0.f;

    CP_WAIT1();          // subchunk 0 resident
    __syncthreads();     // h + W2 buf0 visible to all

#pragma unroll
    for (int s = 0; s < 4; s++) {
        uint32_t wb = smb + EP_W2 + (s & 1) * 4608;
#pragma unroll
        for (int j = 0; j < 2; j++) {
            uint32_t ah[4], al[4];
            uint32_t ao = (wid * 16 + (lane & 15)) * 272
                        + s * 64 + j * 32 + (lane >> 4) * 16;
            LDSM_X4(ah, smb + EP_H_HI + ao);
            LDSM_X4(al, smb + EP_H_LO + ao);
#pragma unroll
            for (int q = 0; q < 4; q++) {
                uint32_t bh[4];
                uint32_t bo = (j * 16 + (lane & 15)) * 144 + q * 32 + (lane >> 4) * 16;
                LDSM_X4T(bh, wb + bo);
                int nq = q * 2;
                MMA16816(ya[nq],     ah, bh[0], bh[1]);
                MMA16816(ya[nq + 1], ah, bh[2], bh[3]);
                MMA16816(ya[nq],     al, bh[0], bh[1]);
                MMA16816(ya[nq + 1], al, bh[2], bh[3]);
            }
        }
        if (s < 2) {
            __syncthreads();                 // buf (s&1) fully consumed by all warps
            if (s + 2 < 4) { STAGE_W2(s & 1, s + 2); CP_COMMIT(); }
            if (s == 0) CP_WAIT1(); else CP_WAIT0();
            __syncthreads();
        } else if (s == 2) {
            CP_WAIT0();
            __syncthreads();
        }
    }
#undef STAGE_W2

    // write 64x64 fp32 partial
    float* yp = d_ypart + (size_t)cc * B_ * OUT_;
#pragma unroll
    for (int n = 0; n < 8; n++) {
        int col = n * 8 + (lane & 3) * 2;
        int r0 = rs + wid * 16 + (lane >> 2);
        if (r0 < re) {
            float2 v = make_float2(ya[n][0], ya[n][1]);
            *reinterpret_cast<float2*>(yp + (size_t)r0 * OUT_ + col) = v;
        }
        int r1 = r0 + 8;
        if (r1 < re) {
            float2 v = make_float2(ya[n][2], ya[n][3]);
            *reinterpret_cast<float2*>(yp + (size_t)r1 * OUT_ + col) = v;
        }
    }

    // ======== deterministic fix-up: last CTA of this tile reduces all chunks ====
    __threadfence();
    __syncthreads();
    if (tid == 0) s_done = atomicAdd(&d_cnt[tile], 1);
    __syncthreads();
    if (s_done == NCHUNK - 1) {
        __threadfence();
        int nrows = re - rs;
        const float* b2g = b2 + g * OUT_;
        for (int u = tid; u < nrows * 16; u += 128) {
            int r = u >> 4;
            int o = (u & 15) * 4;
            int gr = rs + r;
            float4 a = *reinterpret_cast<const float4*>(b2g + o);
#pragma unroll
            for (int c = 0; c < NCHUNK; c++) {
                float4 v = __ldcg(reinterpret_cast<const float4*>(
                    d_ypart + ((size_t)c * B_ + gr) * OUT_ + o));
                a.x += v.x; a.y += v.y; a.z += v.z; a.w += v.w;
            }
            *reinterpret_cast<float4*>(y + (size_t)s_perm[r] * OUT_ + o) = a;
        }
    }
}

// ---------------- launch ----------------
extern "C" void kernel_launch(void* const* d_in, const int* in_sizes, int n_in,
                              void* d_out, int out_size) {
    const float* x   = (const float*)d_in[0];
    const int*   gid = (const int*)  d_in[1];
    const float* W1  = (const float*)d_in[2];
    const float* b1  = (const float*)d_in[3];
    const float* W2  = (const float*)d_in[4];
    const float* b2  = (const float*)d_in[5];
    float* y = (float*)d_out;

    static bool attr_set = false;
    if (!attr_set) {
        cudaFuncSetAttribute(k_gemm, cudaFuncAttributeMaxDynamicSharedMemorySize, SMEM1);
        attr_set = true;
    }

    k_front<<<FR_NB, 1024>>>(gid, x, W1, W2);
    dim3 g1(MAXT1, NCHUNK);
    k_gemm<<<g1, 128, SMEM1>>>(b1, b2, y);
}